// round 10
// baseline (speedup 1.0000x reference)
#include <cuda_runtime.h>
#include <cstdint>

// LMN layer, round 10: 1024 threads/CTA (32 warps, occ 50%) to fix the
// latency-bound profile (everything <40% in ncu at 16 warps).
//   warps = 16 k-groups x 2 col-halves; thread tile 4 rows x BN/4 cols.
//   acc 8 ull + prefetch buffers ~= 60 regs (64-reg budget at 1024 thr).
//   pointer-walk addressing (no wrap masks), predicated prefetch tail.
//   split arrive/wait grid barrier: out[t] store + next-step xW register
//   prefetch overlap the phase2 barrier window.
// Graph: transpose x -> g_xT; transpose m0 -> g_mT; prologue -> g_xWT;
//        persistent recur (128 CTAs x 1024 thr, 2 phases + 2 barriers/step).

#define T_STEPS 512
#define DIM     1024
#define STEP    (64 * 1024)
#define OUTS    ((size_t)T_STEPS * STEP)

typedef unsigned long long ull;

__device__ __align__(256) float g_xT [(size_t)T_STEPS * STEP];  // [t][i][b]
__device__ __align__(256) float g_xWT[(size_t)T_STEPS * STEP];  // [t][n][b]
__device__ __align__(256) float g_mT [STEP];                    // [k][64]
__device__ __align__(256) float g_hT [STEP];                    // [k][64]
__device__ __align__(256) float g_c2T[STEP];                    // [n][64]
__device__ unsigned g_cnt = 0;
__device__ unsigned g_gen = 0;

__device__ __forceinline__ void ffma2(ull& d, ull a, ull b) {
    asm("fma.rn.f32x2 %0, %1, %2, %0;" : "+l"(d) : "l"(a), "l"(b));
}
__device__ __forceinline__ ull addp(ull a, ull b) {
    ull r; asm("add.rn.f32x2 %0, %1, %2;" : "=l"(r) : "l"(a), "l"(b)); return r;
}
__device__ __forceinline__ ull splat(float x) {
    ull r; asm("mov.b64 %0, {%1, %1};" : "=l"(r) : "f"(x), "f"(x)); return r;
}
__device__ __forceinline__ ull packp(float lo, float hi) {
    ull r; asm("mov.b64 %0, {%1, %2};" : "=l"(r) : "f"(lo), "f"(hi)); return r;
}

// smem layout (floats)
constexpr int W1_F  = 1024 * 20;    // w1T [k][20] (16 cols + pad)   80 KB
constexpr int W2_F  = 1024 * 8;     // w2T [k][8]                    32 KB
constexpr int RED_F = 512 * 18 * 2; // 512 pairs x 18 ull slots      72 KB
constexpr int TR_F  = 8 * 66;       // out-transpose tile

// ---------------------------------------------------------------------------
// 64 x BN GEMM tile: C[row,col] = sum_k A[row,k] * W[col,k].
// AT k-major [k][64] in GLOBAL. 1024 thr = 32 warps = 16 kg x 2 col-halves.
// Lane: ro = lane&15 (batch quad 4ro..4ro+3), cw = lane>>4.
// Thread cols: c0 = ch*(BN/2) + cw*(BN/4), C = BN/4 cols.
// acc[rp][c] f32x2 over row pair (2*(2ro)+..): a.x = rows(4ro,4ro+1),
// a.y = rows(4ro+2,4ro+3) -> pair index 2ro+rp.
// Depth-2 A LDG prefetch, depth-1 W LDS prefetch, pointer walks, no wraps.
// Cross-kg smem reduction, epi(col-warp w, rowpair-lane l, f32x2 sum).
// ---------------------------------------------------------------------------
template<int BN, int WP, class Epi>
__device__ __forceinline__ void gemm_tile(const float* __restrict__ AT,
                                          const float* __restrict__ wT,
                                          float* __restrict__ redsm,
                                          Epi epi)
{
    constexpr int C = BN / 4;
    const int tid  = threadIdx.x;
    const int wid  = tid >> 5;
    const int kg   = wid & 15;
    const int ch   = wid >> 4;
    const int lane = tid & 31;
    const int ro   = lane & 15;
    const int cw   = lane >> 4;
    const int c0   = ch * (BN / 2) + cw * C;
    const int kb   = kg << 6;

    const ulonglong2* pA = (const ulonglong2*)AT + (size_t)kb * 16 + ro;
    const float* pW      = wT + (size_t)kb * WP + c0;

    ull acc[2][C];
    #pragma unroll
    for (int rp = 0; rp < 2; ++rp)
        #pragma unroll
        for (int c = 0; c < C; ++c) acc[rp][c] = 0ull;

    // A: depth-2 prefetch (slot = iter&1); k rows kb..kb+3 preloaded
    ulonglong2 aP[2], aQ[2];
    aP[0] = pA[0];  aQ[0] = pA[16];
    aP[1] = pA[32]; aQ[1] = pA[48];

    // W: depth-1 prefetch (k = kb, kb+1)
    float4 wb4[2];
    float2 wb2[2];
    if constexpr (C == 4) {
        wb4[0] = *(const float4*)pW;
        wb4[1] = *(const float4*)(pW + WP);
    } else {
        wb2[0] = *(const float2*)pW;
        wb2[1] = *(const float2*)(pW + WP);
    }

    const ulonglong2* pApf = pA + 64;        // k = kb+4
    const float*      pWpf = pW + 2 * WP;    // k = kb+2

    #pragma unroll 4
    for (int i = 0; i < 32; ++i) {
        const int ib = i & 1;
        #pragma unroll
        for (int kk = 0; kk < 2; ++kk) {
            const ulonglong2 a = kk ? aQ[ib] : aP[ib];
            if constexpr (C == 4) {
                const float4 w4 = wb4[kk];
                ull s0 = splat(w4.x), s1 = splat(w4.y);
                ull s2 = splat(w4.z), s3 = splat(w4.w);
                ffma2(acc[0][0], a.x, s0); ffma2(acc[1][0], a.y, s0);
                ffma2(acc[0][1], a.x, s1); ffma2(acc[1][1], a.y, s1);
                ffma2(acc[0][2], a.x, s2); ffma2(acc[1][2], a.y, s2);
                ffma2(acc[0][3], a.x, s3); ffma2(acc[1][3], a.y, s3);
            } else {
                const float2 w2 = wb2[kk];
                ull s0 = splat(w2.x), s1 = splat(w2.y);
                ffma2(acc[0][0], a.x, s0); ffma2(acc[1][0], a.y, s0);
                ffma2(acc[0][1], a.x, s1); ffma2(acc[1][1], a.y, s1);
            }
        }
        if (i < 31) {                        // W for iter i+1
            if constexpr (C == 4) {
                wb4[0] = *(const float4*)pWpf;
                wb4[1] = *(const float4*)(pWpf + WP);
            } else {
                wb2[0] = *(const float2*)pWpf;
                wb2[1] = *(const float2*)(pWpf + WP);
            }
            pWpf += 2 * WP;
        }
        if (i < 30) {                        // A for iter i+2
            aP[ib] = pApf[0];
            aQ[ib] = pApf[16];
            pApf += 32;
        }
    }

    // cross-k-group reduction (stride-18 ull, slot swizzle <=2-way STS)
    ull* redu = (ull*)redsm;
    const int slot = (kg + ro + cw) & 15;
    #pragma unroll
    for (int rp = 0; rp < 2; ++rp)
        #pragma unroll
        for (int c = 0; c < C; ++c) {
            int pi = (c0 + c) * 32 + 2 * ro + rp;
            redu[(size_t)pi * 18 + slot] = acc[rp][c];
        }
    __syncthreads();

    if (wid < BN) {
        const ulonglong2* r2 =
            (const ulonglong2*)(redu + (size_t)(wid * 32 + lane) * 18);
        ulonglong2 v0 = r2[0], v1 = r2[1], v2 = r2[2], v3 = r2[3];
        ulonglong2 v4 = r2[4], v5 = r2[5], v6 = r2[6], v7 = r2[7];
        ull s = addp(addp(addp(addp(v0.x, v0.y), addp(v1.x, v1.y)),
                          addp(addp(v2.x, v2.y), addp(v3.x, v3.y))),
                     addp(addp(addp(v4.x, v4.y), addp(v5.x, v5.y)),
                          addp(addp(v6.x, v6.y), addp(v7.x, v7.y))));
        epi(wid, lane, s);
    }
    __syncthreads();
}

// -------------------- split grid barrier (128 co-resident CTAs) ------------
__device__ __forceinline__ unsigned bar_arrive()
{
    __syncthreads();
    unsigned gen = 0;
    if (threadIdx.x == 0) {
        asm volatile("ld.acquire.gpu.u32 %0, [%1];" : "=r"(gen) : "l"(&g_gen));
        __threadfence();
        unsigned prev = atomicAdd(&g_cnt, 1u);
        if (prev == gridDim.x - 1) {
            g_cnt = 0;
            asm volatile("st.release.gpu.u32 [%0], %1;"
                         :: "l"(&g_gen), "r"(gen + 1) : "memory");
        }
    }
    return gen;
}
__device__ __forceinline__ void bar_wait(unsigned gen)
{
    if (threadIdx.x == 0) {
        unsigned cur;
        do {
            asm volatile("ld.acquire.gpu.u32 %0, [%1];"
                         : "=r"(cur) : "l"(&g_gen));
        } while (cur == gen);
    }
    __syncthreads();
}
__device__ __forceinline__ void grid_sync() { bar_wait(bar_arrive()); }

// ---------------- 64x64-tile transpose: dst[t][i][b] = src[t][b][i] ---------
__global__ void __launch_bounds__(256) transpose_k(const float* __restrict__ src,
                                                   float* __restrict__ dst)
{
    __shared__ float sm[64 * 65];
    const int t = blockIdx.y, i0 = blockIdx.x * 64, tid = threadIdx.x;
    const float* s = src + (size_t)t * STEP;
    float* d       = dst + (size_t)t * STEP;
    #pragma unroll
    for (int j = 0; j < 16; ++j) {
        int e = j * 256 + tid, b = e >> 6, i = e & 63;
        sm[b * 65 + i] = s[(size_t)b * DIM + i0 + i];
    }
    __syncthreads();
    #pragma unroll
    for (int j = 0; j < 16; ++j) {
        int e = j * 256 + tid, i = e >> 6, b = e & 63;
        d[(size_t)(i0 + i) * 64 + b] = sm[b * 65 + i];
    }
}

// ---------------- prologue: g_xWT[t] = (x[t] @ Wxh^T + bh)^T ----------------
__global__ void __launch_bounds__(1024, 1) prologue_k(const float* __restrict__ Wxh,
                                                      const float* __restrict__ bh)
{
    extern __shared__ float sm[];
    float* w1  = sm;
    float* red = sm + W1_F;
    const int cx = blockIdx.x, tid = threadIdx.x;
    for (int e = tid; e < 16 * DIM; e += 1024) {
        int c = e >> 10, k = e & 1023;
        w1[k * 20 + c] = Wxh[(size_t)(cx * 16 + c) * DIM + k];
    }
    __syncthreads();
    const int nb = cx * 16;
    #pragma unroll 1
    for (int i = 0; i < 4; ++i) {
        int t = blockIdx.y * 4 + i;
        const float* AT = g_xT + (size_t)t * STEP;
        float* xo       = g_xWT + (size_t)t * STEP;
        gemm_tile<16, 20>(AT, w1, red, [&](int w, int l, ull s) {
            int n = nb + w;
            *(ull*)(xo + (size_t)n * 64 + 2 * l) = addp(s, splat(bh[n]));
        });
    }
}

// ---------------- persistent recurrence ------------------------------------
__global__ void __launch_bounds__(1024, 1) recur_k(const float* __restrict__ Whm,
                                                   const float* __restrict__ Wmm,
                                                   const float* __restrict__ Wmh,
                                                   const float* __restrict__ bm,
                                                   float* __restrict__ out)
{
    extern __shared__ float sm[];
    float* w1   = sm;                       // [k][20]
    float* w2   = sm + W1_F;                // [k][8]
    float* red  = sm + W1_F + W2_F;
    float* trsm = sm + W1_F + W2_F + RED_F; // [8][66]
    const int b = blockIdx.x, tid = threadIdx.x;
    const int wid = tid >> 5, lane = tid & 31;

    const float* W1 = (b < 64) ? (Wmh + (size_t)b * 16 * DIM)
                               : (Wmm + (size_t)(b - 64) * 16 * DIM);
    for (int e = tid; e < 16 * DIM; e += 1024) {
        int c = e >> 10, k = e & 1023;
        w1[k * 20 + c] = W1[(size_t)c * DIM + k];
    }
    for (int e = tid; e < 8 * DIM; e += 1024) {
        int c = e >> 10, k = e & 1023;
        w2[k * 8 + c] = Whm[(size_t)b * 8 * DIM + (size_t)c * DIM + k];
    }
    __syncthreads();

    const int nb1 = (b & 63) * 16;
    const int nb2 = b * 8;
    const bool hq = (b < 64);

    // hoisted per-thread constants
    ull bmsp = 0;
    if (wid < 8) bmsp = splat(bm[nb2 + wid]);
    ull xwbuf = 0;
    if (hq && wid < 16)
        xwbuf = *(const ull*)(g_xWT + (size_t)(nb1 + wid) * 64 + 2 * lane);

    #pragma unroll 1
    for (int t = 0; t < T_STEPS; ++t) {
        // phase1: h^T (CTAs 0-63) / c2^T (CTAs 64-127)
        gemm_tile<16, 20>(g_mT, w1, red, [&](int w, int l, ull s) {
            int n = nb1 + w;
            if (hq) {
                ull v = addp(s, xwbuf);
                float lo = __uint_as_float((unsigned)v);
                float hi = __uint_as_float((unsigned)(v >> 32));
                *(ull*)(g_hT + (size_t)n * 64 + 2 * l) =
                    packp(tanhf(lo), tanhf(hi));
            } else {
                *(ull*)(g_c2T + (size_t)n * 64 + 2 * l) = s;
            }
        });
        grid_sync();

        // phase2: m' = h@Whm^T + c2 + bm  -> g_mT + trsm
        gemm_tile<8, 8>(g_hT, w2, red, [&](int w, int l, ull s) {
            int n = nb2 + w;
            ull c2 = *(const ull*)(g_c2T + (size_t)n * 64 + 2 * l);
            ull v  = addp(addp(s, c2), bmsp);
            *(ull*)(g_mT + (size_t)n * 64 + 2 * l) = v;
            *(ull*)(trsm + w * 66 + 2 * l) = v;
        });

        // arrive, then overlap out-store + next-step xW prefetch with the wait
        unsigned gen = bar_arrive();
        if (tid < 512) {
            int bb = tid >> 3, c = tid & 7;
            float v = trsm[c * 66 + bb];
            out[(size_t)t * STEP + (size_t)bb * DIM + nb2 + c] = v;
            if (t == T_STEPS - 1)
                out[OUTS + (size_t)bb * DIM + nb2 + c] = v;     // m_final
        }
        if (hq && wid < 16 && t + 1 < T_STEPS)
            xwbuf = *(const ull*)(g_xWT + (size_t)(t + 1) * STEP
                                  + (size_t)(nb1 + wid) * 64 + 2 * lane);
        bar_wait(gen);
    }
}

#define PRO_SMEM ((W1_F + RED_F) * 4)                   // 155648 B
#define PER_SMEM ((W1_F + W2_F + RED_F + TR_F) * 4)     // 190592 B

extern "C" void kernel_launch(void* const* d_in, const int* in_sizes, int n_in,
                              void* d_out, int out_size)
{
    const float* x      = (const float*)d_in[0];
    const float* m_prev = (const float*)d_in[1];
    const float* Wxh    = (const float*)d_in[2];
    const float* Whm    = (const float*)d_in[3];
    const float* Wmm    = (const float*)d_in[4];
    const float* Wmh    = (const float*)d_in[5];
    const float* bh     = (const float*)d_in[6];
    const float* bm     = (const float*)d_in[7];
    float* out = (float*)d_out;

    cudaFuncSetAttribute(prologue_k,
                         cudaFuncAttributeMaxDynamicSharedMemorySize, PRO_SMEM);
    cudaFuncSetAttribute(recur_k,
                         cudaFuncAttributeMaxDynamicSharedMemorySize, PER_SMEM);

    float* d_gxT; cudaGetSymbolAddress((void**)&d_gxT, g_xT);
    float* d_gmT; cudaGetSymbolAddress((void**)&d_gmT, g_mT);

    transpose_k<<<dim3(16, 512), 256>>>(x, d_gxT);          // x  -> g_xT
    transpose_k<<<dim3(16, 1), 256>>>(m_prev, d_gmT);       // m0 -> g_mT
    prologue_k<<<dim3(64, 128), 1024, PRO_SMEM>>>(Wxh, bh);
    recur_k<<<128, 1024, PER_SMEM>>>(Whm, Wmm, Wmh, bm, out);
}